// round 1
// baseline (speedup 1.0000x reference)
#include <cuda_runtime.h>
#include <cuda_bf16.h>
#include <math.h>

// Problem constants
#define N_TOK 32768
#define HDIM  1152
#define LIGHT 1152
#define HEAVY 4608

// Static scratch (allocation-free rule): intermediates + router probs
__device__ float g_hl[(size_t)N_TOK * LIGHT];   // gelu(x @ light_w1^T + b1)  : 151 MB
__device__ float g_hh[(size_t)N_TOK * HEAVY];   // gelu(x @ heavy_w1^T + b1)  : 604 MB
__device__ float g_probs[2 * N_TOK];            // softmax router probs [N][2]

__device__ __forceinline__ float gelu_exact(float v) {
    return 0.5f * v * (1.0f + erff(v * 0.70710678118654752f));
}

// -------------------- router: logits -> softmax probs --------------------
// one warp per token
__global__ void router_kernel(const float* __restrict__ x,
                              const float* __restrict__ rw,
                              const float* __restrict__ rb,
                              float* __restrict__ probs) {
    int warp = (blockIdx.x * blockDim.x + threadIdx.x) >> 5;
    int lane = threadIdx.x & 31;
    if (warp >= N_TOK) return;
    const float* xp = x + (size_t)warp * HDIM;
    float a0 = 0.f, a1 = 0.f;
    #pragma unroll 4
    for (int h = lane; h < HDIM; h += 32) {
        float v = xp[h];
        a0 = fmaf(v, rw[h], a0);
        a1 = fmaf(v, rw[HDIM + h], a1);
    }
    #pragma unroll
    for (int off = 16; off; off >>= 1) {
        a0 += __shfl_xor_sync(0xffffffffu, a0, off);
        a1 += __shfl_xor_sync(0xffffffffu, a1, off);
    }
    if (lane == 0) {
        a0 += rb[0];
        a1 += rb[1];
        float m  = fmaxf(a0, a1);
        float e0 = __expf(a0 - m), e1 = __expf(a1 - m);
        float inv = 1.0f / (e0 + e1);
        probs[2 * warp]     = e0 * inv;
        probs[2 * warp + 1] = e1 * inv;
    }
}

// -------------------- NT SGEMM: C[n,m] = epilogue(sum_k A[n,k]*W[m,k] + b[m]) ----
// MODE 0: C = gelu(acc + bias)                       (fc1)
// MODE 1: C = p[n,expert] * (acc + bias)             (fc2, first expert, overwrite)
// MODE 2: C += p[n,expert] * (acc + bias)            (fc2, second expert, accumulate)
// Tiles: BM=BN=128, BK=8, 256 threads, 8x8 per-thread.
// Requires: N_TOK % 128 == 0, M % 128 == 0, K % 8 == 0 (all hold here).
template <int MODE>
__global__ void __launch_bounds__(256) sgemm_nt_kernel(
    const float* __restrict__ A,      // [N_TOK, K] row-major
    const float* __restrict__ W,      // [M, K] row-major
    const float* __restrict__ bias,   // [M]
    float* __restrict__ C,            // [N_TOK, M]
    const float* __restrict__ probs,  // [N_TOK, 2] (MODE 1/2)
    int expert, int M, int K)
{
    __shared__ float As[8][128];
    __shared__ float Ws[8][128];

    const int tid  = threadIdx.x;
    const int row0 = blockIdx.y * 128;   // token tile
    const int col0 = blockIdx.x * 128;   // output-feature tile

    // global load mapping: 256 threads load 128x8 floats = 1 float4 each
    const int lr = tid >> 1;             // 0..127 : row within tile
    const int lc = (tid & 1) * 4;        // 0 or 4 : k-offset
    const float* Aptr = A + (size_t)(row0 + lr) * K + lc;
    const float* Wptr = W + (size_t)(col0 + lr) * K + lc;

    const int tx = tid & 15;             // 0..15 -> 8 output cols each
    const int ty = tid >> 4;             // 0..15 -> 8 output rows each

    float acc[8][8];
    #pragma unroll
    for (int i = 0; i < 8; i++)
        #pragma unroll
        for (int j = 0; j < 8; j++) acc[i][j] = 0.f;

    for (int k0 = 0; k0 < K; k0 += 8) {
        float4 av = *(const float4*)(Aptr + k0);
        float4 wv = *(const float4*)(Wptr + k0);
        As[lc + 0][lr] = av.x; As[lc + 1][lr] = av.y;
        As[lc + 2][lr] = av.z; As[lc + 3][lr] = av.w;
        Ws[lc + 0][lr] = wv.x; Ws[lc + 1][lr] = wv.y;
        Ws[lc + 2][lr] = wv.z; Ws[lc + 3][lr] = wv.w;
        __syncthreads();

        #pragma unroll
        for (int kk = 0; kk < 8; kk++) {
            float ra[8], rb[8];
            *(float4*)(ra)     = *(const float4*)&As[kk][ty * 8];
            *(float4*)(ra + 4) = *(const float4*)&As[kk][ty * 8 + 4];
            *(float4*)(rb)     = *(const float4*)&Ws[kk][tx * 8];
            *(float4*)(rb + 4) = *(const float4*)&Ws[kk][tx * 8 + 4];
            #pragma unroll
            for (int i = 0; i < 8; i++)
                #pragma unroll
                for (int j = 0; j < 8; j++)
                    acc[i][j] = fmaf(ra[i], rb[j], acc[i][j]);
        }
        __syncthreads();
    }

    // epilogue
    #pragma unroll
    for (int i = 0; i < 8; i++) {
        const int n = row0 + ty * 8 + i;
        float p = 0.f;
        if (MODE != 0) p = probs[2 * n + expert];
        float* crow = C + (size_t)n * M + col0 + tx * 8;
        #pragma unroll
        for (int j = 0; j < 8; j++) {
            const int m = col0 + tx * 8 + j;
            float v = acc[i][j] + bias[m];
            if (MODE == 0)      crow[j] = gelu_exact(v);
            else if (MODE == 1) crow[j] = p * v;
            else                crow[j] += p * v;
        }
    }
}

extern "C" void kernel_launch(void* const* d_in, const int* in_sizes, int n_in,
                              void* d_out, int out_size) {
    const float* x        = (const float*)d_in[0];
    const float* router_w = (const float*)d_in[1];
    const float* router_b = (const float*)d_in[2];
    const float* light_w1 = (const float*)d_in[3];
    const float* light_b1 = (const float*)d_in[4];
    const float* light_w2 = (const float*)d_in[5];
    const float* light_b2 = (const float*)d_in[6];
    const float* heavy_w1 = (const float*)d_in[7];
    const float* heavy_b1 = (const float*)d_in[8];
    const float* heavy_w2 = (const float*)d_in[9];
    const float* heavy_b2 = (const float*)d_in[10];
    float* out = (float*)d_out;

    float* hl;    cudaGetSymbolAddress((void**)&hl, g_hl);
    float* hh;    cudaGetSymbolAddress((void**)&hh, g_hh);
    float* probs; cudaGetSymbolAddress((void**)&probs, g_probs);

    // router probs
    router_kernel<<<N_TOK / 8, 256>>>(x, router_w, router_b, probs);

    // fc1 (gelu fused)
    {
        dim3 grid(LIGHT / 128, N_TOK / 128);
        sgemm_nt_kernel<0><<<grid, 256>>>(x, light_w1, light_b1, hl, nullptr, 0, LIGHT, HDIM);
    }
    {
        dim3 grid(HEAVY / 128, N_TOK / 128);
        sgemm_nt_kernel<0><<<grid, 256>>>(x, heavy_w1, heavy_b1, hh, nullptr, 0, HEAVY, HDIM);
    }

    // fc2 (prob-weighted combine fused)
    {
        dim3 grid(HDIM / 128, N_TOK / 128);
        sgemm_nt_kernel<1><<<grid, 256>>>(hl, light_w2, light_b2, out, probs, 0, HDIM, LIGHT);
    }
    {
        dim3 grid(HDIM / 128, N_TOK / 128);
        sgemm_nt_kernel<2><<<grid, 256>>>(hh, heavy_w2, heavy_b2, out, probs, 1, HDIM, HEAVY);
    }
}

// round 3
// speedup vs baseline: 2.0229x; 2.0229x over previous
#include <cuda_runtime.h>
#include <cuda_bf16.h>
#include <math.h>
#include <stdint.h>

// ---------------- problem constants ----------------
#define N_TOK 32768
#define HDIM  1152
#define LIGHT 1152
#define HEAVY 4608

// ---------------- static scratch ----------------
__device__ float g_hl[(size_t)N_TOK * LIGHT];
__device__ float g_hh[(size_t)N_TOK * HEAVY];
__device__ float g_probs[2 * N_TOK];

__device__ __forceinline__ uint32_t cvt_tf32(float f) {
    uint32_t u;
    asm("cvt.rna.tf32.f32 %0, %1;" : "=r"(u) : "f"(f));
    return u;
}

__device__ __forceinline__ void mma_tf32(float* d, const uint32_t* a, const uint32_t* b) {
    asm volatile(
        "mma.sync.aligned.m16n8k8.row.col.f32.tf32.tf32.f32 "
        "{%0,%1,%2,%3}, {%4,%5,%6,%7}, {%8,%9}, {%0,%1,%2,%3};"
        : "+f"(d[0]), "+f"(d[1]), "+f"(d[2]), "+f"(d[3])
        : "r"(a[0]), "r"(a[1]), "r"(a[2]), "r"(a[3]), "r"(b[0]), "r"(b[1]));
}

__device__ __forceinline__ float gelu_exact(float v) {
    return 0.5f * v * (1.0f + erff(v * 0.70710678118654752f));
}

// -------------------- router --------------------
__global__ void router_kernel(const float* __restrict__ x,
                              const float* __restrict__ rw,
                              const float* __restrict__ rb,
                              float* __restrict__ probs) {
    int warp = (blockIdx.x * blockDim.x + threadIdx.x) >> 5;
    int lane = threadIdx.x & 31;
    if (warp >= N_TOK) return;
    const float* xp = x + (size_t)warp * HDIM;
    float a0 = 0.f, a1 = 0.f;
    #pragma unroll 4
    for (int h = lane; h < HDIM; h += 32) {
        float v = xp[h];
        a0 = fmaf(v, rw[h], a0);
        a1 = fmaf(v, rw[HDIM + h], a1);
    }
    #pragma unroll
    for (int off = 16; off; off >>= 1) {
        a0 += __shfl_xor_sync(0xffffffffu, a0, off);
        a1 += __shfl_xor_sync(0xffffffffu, a1, off);
    }
    if (lane == 0) {
        a0 += rb[0];
        a1 += rb[1];
        float m = fmaxf(a0, a1);
        float e0 = __expf(a0 - m), e1 = __expf(a1 - m);
        float inv = 1.0f / (e0 + e1);
        probs[2 * warp]     = e0 * inv;
        probs[2 * warp + 1] = e1 * inv;
    }
}

// -------------------- tf32 mma.sync GEMM --------------------
// C[n,m] = epi( sum_k A[n,k]*W[m,k] + bias[m] )
// BM=128 tokens x BN=128 features x BK=32; 256 threads, 8 warps (2x4),
// warp tile 64x32, mma m16n8k8 tf32.
// Shared layout (conflict-free for STS.128 + all fragment LDS.32):
//   elem(row, k) at  row*32 + ((k + 4*row) & 31)
// MODE 0: gelu; MODE 1: p*(.) overwrite; MODE 2: += p*(.)
#define STAGE_F 8192  // floats per stage (A 4096 + W 4096)

template <int MODE>
__global__ void __launch_bounds__(256, 2) gemm_mma_kernel(
    const float* __restrict__ A, const float* __restrict__ W,
    const float* __restrict__ bias, float* __restrict__ C,
    const float* __restrict__ probs, int expert, int Nfeat, int K)
{
    extern __shared__ float sm[];
    const int tid  = threadIdx.x;
    const int wid  = tid >> 5, lane = tid & 31;
    const int wr   = wid >> 2;          // 0..1 : 64-row group
    const int wn   = wid & 3;           // 0..3 : 32-col group
    const int g    = lane >> 2;         // 0..7
    const int c    = lane & 3;          // 0..3
    const int row0 = blockIdx.y * 128;
    const int col0 = blockIdx.x * 128;

    const int lrow = tid >> 3;          // 0..31 (+ i*32)
    const int lkc  = (tid & 7) * 4;     // 0,4,...,28

    const float* Abase = A + (size_t)row0 * K + lkc;
    const float* Wbase = W + (size_t)col0 * K + lkc;

    float acc[4][4][4];
    #pragma unroll
    for (int i = 0; i < 4; i++)
        #pragma unroll
        for (int j = 0; j < 4; j++)
            #pragma unroll
            for (int q = 0; q < 4; q++) acc[i][j][q] = 0.f;

    auto ldgA = [&](int k0, float4* buf) {
        #pragma unroll
        for (int i = 0; i < 4; i++)
            buf[i] = *(const float4*)(Abase + (size_t)(lrow + i * 32) * K + k0);
    };
    auto ldgW = [&](int k0, float4* buf) {
        #pragma unroll
        for (int i = 0; i < 4; i++)
            buf[i] = *(const float4*)(Wbase + (size_t)(lrow + i * 32) * K + k0);
    };
    auto stsA = [&](int s, const float4* buf) {
        float* As = sm + s * STAGE_F;
        #pragma unroll
        for (int i = 0; i < 4; i++) {
            int r = lrow + i * 32;
            int off = r * 32 + ((lkc + r * 4) & 31);
            uint4 u = make_uint4(cvt_tf32(buf[i].x), cvt_tf32(buf[i].y),
                                 cvt_tf32(buf[i].z), cvt_tf32(buf[i].w));
            *(uint4*)(As + off) = u;
        }
    };
    auto stsW = [&](int s, const float4* buf) {
        float* Ws = sm + s * STAGE_F + 4096;
        #pragma unroll
        for (int i = 0; i < 4; i++) {
            int r = lrow + i * 32;
            int off = r * 32 + ((lkc + r * 4) & 31);
            uint4 u = make_uint4(cvt_tf32(buf[i].x), cvt_tf32(buf[i].y),
                                 cvt_tf32(buf[i].z), cvt_tf32(buf[i].w));
            *(uint4*)(Ws + off) = u;
        }
    };
    auto compute_half = [&](int s, int h) {
        const float* As = sm + s * STAGE_F;
        const float* Ws = As + 4096;
        #pragma unroll
        for (int ks = h * 2; ks < h * 2 + 2; ks++) {
            uint32_t af[4][4];
            uint32_t bf[4][2];
            #pragma unroll
            for (int i = 0; i < 4; i++) {
                int rowA = wr * 64 + i * 16 + g;
                int base = rowA * 32;
                int o0 = (ks * 8 + c + rowA * 4) & 31;
                int o2 = (o0 + 4) & 31;
                af[i][0] = __float_as_uint(As[base + o0]);
                af[i][1] = __float_as_uint(As[base + 256 + o0]);
                af[i][2] = __float_as_uint(As[base + o2]);
                af[i][3] = __float_as_uint(As[base + 256 + o2]);
            }
            #pragma unroll
            for (int j = 0; j < 4; j++) {
                int nB = wn * 32 + j * 8 + g;
                int baseB = nB * 32;
                int o0 = (ks * 8 + c + nB * 4) & 31;
                int o1 = (o0 + 4) & 31;
                bf[j][0] = __float_as_uint(Ws[baseB + o0]);
                bf[j][1] = __float_as_uint(Ws[baseB + o1]);
            }
            #pragma unroll
            for (int i = 0; i < 4; i++)
                #pragma unroll
                for (int j = 0; j < 4; j++)
                    mma_tf32(acc[i][j], af[i], bf[j]);
        }
    };

    const int KT = K >> 5;
    float4 bufA[4], bufW[4];
    ldgA(0, bufA);
    ldgW(0, bufW);
    stsA(0, bufA);
    stsW(0, bufW);
    __syncthreads();

    for (int kt = 0; kt < KT; kt++) {
        const int cur = kt & 1;
        const int k1  = (kt + 1) * 32;
        if (kt + 1 < KT) ldgA(k1, bufA);
        compute_half(cur, 0);
        if (kt + 1 < KT) { stsA(cur ^ 1, bufA); ldgW(k1, bufW); }
        compute_half(cur, 1);
        if (kt + 1 < KT) stsW(cur ^ 1, bufW);
        __syncthreads();
    }

    // -------- epilogue --------
    #pragma unroll
    for (int i = 0; i < 4; i++) {
        const int rowA = row0 + wr * 64 + i * 16 + g;
        float p0 = 0.f, p1 = 0.f;
        if (MODE != 0) {
            p0 = probs[2 * rowA + expert];
            p1 = probs[2 * (rowA + 8) + expert];
        }
        #pragma unroll
        for (int j = 0; j < 4; j++) {
            const int col = col0 + wn * 32 + j * 8 + c * 2;
            const float b0 = bias[col], b1 = bias[col + 1];
            float* out0 = C + (size_t)rowA * Nfeat + col;
            float* out1 = C + (size_t)(rowA + 8) * Nfeat + col;
            float v00 = acc[i][j][0] + b0, v01 = acc[i][j][1] + b1;
            float v10 = acc[i][j][2] + b0, v11 = acc[i][j][3] + b1;
            if (MODE == 0) {
                out0[0] = gelu_exact(v00); out0[1] = gelu_exact(v01);
                out1[0] = gelu_exact(v10); out1[1] = gelu_exact(v11);
            } else if (MODE == 1) {
                out0[0] = p0 * v00; out0[1] = p0 * v01;
                out1[0] = p1 * v10; out1[1] = p1 * v11;
            } else {
                out0[0] += p0 * v00; out0[1] += p0 * v01;
                out1[0] += p1 * v10; out1[1] += p1 * v11;
            }
        }
    }
}

#define SMEM_BYTES (2 * STAGE_F * sizeof(float))

// -------------------- launch --------------------
extern "C" void kernel_launch(void* const* d_in, const int* in_sizes, int n_in,
                              void* d_out, int out_size) {
    const float* x        = (const float*)d_in[0];
    const float* router_w = (const float*)d_in[1];
    const float* router_b = (const float*)d_in[2];
    const float* light_w1 = (const float*)d_in[3];
    const float* light_b1 = (const float*)d_in[4];
    const float* light_w2 = (const float*)d_in[5];
    const float* light_b2 = (const float*)d_in[6];
    const float* heavy_w1 = (const float*)d_in[7];
    const float* heavy_b1 = (const float*)d_in[8];
    const float* heavy_w2 = (const float*)d_in[9];
    const float* heavy_b2 = (const float*)d_in[10];
    float* out = (float*)d_out;

    float* hl;    cudaGetSymbolAddress((void**)&hl, g_hl);
    float* hh;    cudaGetSymbolAddress((void**)&hh, g_hh);
    float* probs; cudaGetSymbolAddress((void**)&probs, g_probs);

    static bool attr_done = false;
    if (!attr_done) {
        cudaFuncSetAttribute(gemm_mma_kernel<0>, cudaFuncAttributeMaxDynamicSharedMemorySize, SMEM_BYTES);
        cudaFuncSetAttribute(gemm_mma_kernel<1>, cudaFuncAttributeMaxDynamicSharedMemorySize, SMEM_BYTES);
        cudaFuncSetAttribute(gemm_mma_kernel<2>, cudaFuncAttributeMaxDynamicSharedMemorySize, SMEM_BYTES);
        attr_done = true;
    }

    router_kernel<<<N_TOK / 8, 256>>>(x, router_w, router_b, probs);

    // fc1 (gelu fused)
    {
        dim3 grid(LIGHT / 128, N_TOK / 128);
        gemm_mma_kernel<0><<<grid, 256, SMEM_BYTES>>>(x, light_w1, light_b1, hl, nullptr, 0, LIGHT, HDIM);
    }
    {
        dim3 grid(HEAVY / 128, N_TOK / 128);
        gemm_mma_kernel<0><<<grid, 256, SMEM_BYTES>>>(x, heavy_w1, heavy_b1, hh, nullptr, 0, HEAVY, HDIM);
    }
    // fc2 (prob-weighted combine fused)
    {
        dim3 grid(HDIM / 128, N_TOK / 128);
        gemm_mma_kernel<1><<<grid, 256, SMEM_BYTES>>>(hl, light_w2, light_b2, out, probs, 0, HDIM, LIGHT);
    }
    {
        dim3 grid(HDIM / 128, N_TOK / 128);
        gemm_mma_kernel<2><<<grid, 256, SMEM_BYTES>>>(hh, heavy_w2, heavy_b2, out, probs, 1, HDIM, HEAVY);
    }
}

// round 4
// speedup vs baseline: 3.8451x; 1.9008x over previous
#include <cuda_runtime.h>
#include <cuda_bf16.h>
#include <math.h>
#include <stdint.h>

// ---------------- problem constants ----------------
#define N_TOK 32768
#define HDIM  1152
#define LIGHT 1152
#define HEAVY 4608

// ---------------- static scratch ----------------
__device__ float g_hl[(size_t)N_TOK * LIGHT];
__device__ float g_hh[(size_t)N_TOK * HEAVY];
__device__ float g_probs[2 * N_TOK];
__device__ float g_xr [(size_t)N_TOK * HDIM];
__device__ float g_lw1r[(size_t)LIGHT * HDIM];
__device__ float g_hw1r[(size_t)HEAVY * HDIM];
__device__ float g_lw2r[(size_t)HDIM * LIGHT];
__device__ float g_hw2r[(size_t)HDIM * HEAVY];

__device__ __forceinline__ uint32_t cvt_tf32(float f) {
    uint32_t u;
    asm("cvt.rna.tf32.f32 %0, %1;" : "=r"(u) : "f"(f));
    return u;
}
__device__ __forceinline__ uint32_t smem_u32(const void* p) {
    uint32_t a;
    asm("{ .reg .u64 t; cvta.to.shared.u64 t, %1; cvt.u32.u64 %0, t; }" : "=r"(a) : "l"(p));
    return a;
}
__device__ __forceinline__ void cp_async16(uint32_t s, const float* g) {
    size_t gp = __cvta_generic_to_global(g);
    asm volatile("cp.async.cg.shared.global [%0], [%1], 16;" :: "r"(s), "l"(gp) : "memory");
}
#define CP_COMMIT() asm volatile("cp.async.commit_group;" ::: "memory")
#define CP_WAIT1()  asm volatile("cp.async.wait_group 1;" ::: "memory")
#define CP_WAIT0()  asm volatile("cp.async.wait_group 0;" ::: "memory")

__device__ __forceinline__ void mma_tf32(float* d, const uint32_t* a, const uint32_t* b) {
    asm volatile(
        "mma.sync.aligned.m16n8k8.row.col.f32.tf32.tf32.f32 "
        "{%0,%1,%2,%3}, {%4,%5,%6,%7}, {%8,%9}, {%0,%1,%2,%3};"
        : "+f"(d[0]), "+f"(d[1]), "+f"(d[2]), "+f"(d[3])
        : "r"(a[0]), "r"(a[1]), "r"(a[2]), "r"(a[3]), "r"(b[0]), "r"(b[1]));
}

__device__ __forceinline__ float gelu_exact(float v) {
    return 0.5f * v * (1.0f + erff(v * 0.70710678118654752f));
}

// swizzle: float4-slot s at row r stored at slot (s ^ FSW(r&7));
// FSW maps consecutive rows to slots differing in bit2 -> LDS.128 phases conflict-free
#define FSW(e) ((((e) & 1) << 2) | ((e) >> 1))

// -------------------- elementwise tf32 pre-round --------------------
__global__ void round_kernel(const float* __restrict__ in, float* __restrict__ outp, int n4) {
    int i = blockIdx.x * blockDim.x + threadIdx.x;
    if (i < n4) {
        float4 v = ((const float4*)in)[i];
        uint4 u = make_uint4(cvt_tf32(v.x), cvt_tf32(v.y), cvt_tf32(v.z), cvt_tf32(v.w));
        ((uint4*)outp)[i] = u;
    }
}

// -------------------- router --------------------
__global__ void router_kernel(const float* __restrict__ x,
                              const float* __restrict__ rw,
                              const float* __restrict__ rb,
                              float* __restrict__ probs) {
    int warp = (blockIdx.x * blockDim.x + threadIdx.x) >> 5;
    int lane = threadIdx.x & 31;
    if (warp >= N_TOK) return;
    const float* xp = x + (size_t)warp * HDIM;
    float a0 = 0.f, a1 = 0.f;
    #pragma unroll 4
    for (int h = lane; h < HDIM; h += 32) {
        float v = xp[h];
        a0 = fmaf(v, rw[h], a0);
        a1 = fmaf(v, rw[HDIM + h], a1);
    }
    #pragma unroll
    for (int off = 16; off; off >>= 1) {
        a0 += __shfl_xor_sync(0xffffffffu, a0, off);
        a1 += __shfl_xor_sync(0xffffffffu, a1, off);
    }
    if (lane == 0) {
        a0 += rb[0];
        a1 += rb[1];
        float m = fmaxf(a0, a1);
        float e0 = __expf(a0 - m), e1 = __expf(a1 - m);
        float inv = 1.0f / (e0 + e1);
        probs[2 * warp]     = e0 * inv;
        probs[2 * warp + 1] = e1 * inv;
    }
}

// -------------------- tf32 mma.sync GEMM (cp.async pipelined) --------------------
// Inputs MUST be pre-rounded to tf32 (raw 16B cp.async, no cvt in loop).
// BM=128 x BN=128 x BK=32, 256 threads (8 warps 2x4), warp tile 64x32.
// Shared stage: A 128x32 fl + W 128x32 fl = 8192 floats; 3 stages (96KB).
// MODE 0: gelu (output tf32-rounded); MODE 1: p*(.) overwrite; MODE 2: += p*(.)
#define STAGE_F 8192
#define STAGE_B (STAGE_F * 4)
#define SMEM_BYTES (3 * STAGE_B)

template <int MODE>
__global__ void __launch_bounds__(256, 2) gemm_cp_kernel(
    const float* __restrict__ A, const float* __restrict__ W,
    const float* __restrict__ bias, float* __restrict__ C,
    const float* __restrict__ probs, int expert, int Nfeat, int K)
{
    extern __shared__ float sm[];
    const int tid  = threadIdx.x;
    const int wid  = tid >> 5, lane = tid & 31;
    const int wr   = wid >> 2;      // 0..1
    const int wn   = wid & 3;       // 0..3
    const int g    = lane >> 2;     // 0..7
    const int c    = lane & 3;      // 0..3
    const int row0 = blockIdx.y * 128;
    const int col0 = blockIdx.x * 128;

    // cp.async mapping: tid -> (lrow = tid>>3 in 0..31, k4 = tid&7)
    const int lrow = tid >> 3;
    const int k4   = tid & 7;
    const uint32_t sbase = smem_u32(sm);
    const uint32_t swzB  = (uint32_t)((k4 ^ FSW(lrow & 7)) * 16);

    uint32_t dstA[4], dstW[4];
    #pragma unroll
    for (int i = 0; i < 4; i++) {
        dstA[i] = sbase + (uint32_t)((lrow + i * 32) * 128) + swzB;
        dstW[i] = dstA[i] + 16384u;
    }
    const float* srcA0 = A + (size_t)(row0 + lrow) * K + k4 * 4;
    const float* srcW0 = W + (size_t)(col0 + lrow) * K + k4 * 4;

    float acc[4][4][4];
    #pragma unroll
    for (int i = 0; i < 4; i++)
        #pragma unroll
        for (int j = 0; j < 4; j++)
            #pragma unroll
            for (int q = 0; q < 4; q++) acc[i][j][q] = 0.f;

    auto issue = [&](int kt) {
        const uint32_t so = (uint32_t)(kt % 3) * STAGE_B;
        const int ko = kt * 32;
        #pragma unroll
        for (int i = 0; i < 4; i++) {
            cp_async16(dstA[i] + so, srcA0 + (size_t)(i * 32) * K + ko);
            cp_async16(dstW[i] + so, srcW0 + (size_t)(i * 32) * K + ko);
        }
    };

    auto compute = [&](int st) {
        const float* As = sm + st * STAGE_F;
        const float* Ws = As + 4096;
        #pragma unroll
        for (int g16 = 0; g16 < 2; g16++) {
            const int slot = ((g16 * 4 + c) ^ FSW(g)) * 4;
            float4 a0[4], a1[4];
            #pragma unroll
            for (int i = 0; i < 4; i++) {
                const int r0 = wr * 64 + i * 16 + g;
                a0[i] = *(const float4*)(As + r0 * 32 + slot);
                a1[i] = *(const float4*)(As + (r0 + 8) * 32 + slot);
            }
            #pragma unroll
            for (int j = 0; j < 4; j++) {
                const int n0 = wn * 32 + j * 8 + g;
                float4 bv = *(const float4*)(Ws + n0 * 32 + slot);
                const float* bp = (const float*)&bv;
                #pragma unroll
                for (int s = 0; s < 2; s++) {
                    uint32_t bb[2] = { __float_as_uint(bp[2 * s]),
                                       __float_as_uint(bp[2 * s + 1]) };
                    #pragma unroll
                    for (int i = 0; i < 4; i++) {
                        const float* p0 = (const float*)&a0[i];
                        const float* p1 = (const float*)&a1[i];
                        uint32_t aa[4] = { __float_as_uint(p0[2 * s]),
                                           __float_as_uint(p1[2 * s]),
                                           __float_as_uint(p0[2 * s + 1]),
                                           __float_as_uint(p1[2 * s + 1]) };
                        mma_tf32(acc[i][j], aa, bb);
                    }
                }
            }
        }
    };

    const int KT = K >> 5;
    issue(0); CP_COMMIT();
    issue(1); CP_COMMIT();

    for (int kt = 0; kt < KT; kt++) {
        CP_WAIT1();
        __syncthreads();
        if (kt + 2 < KT) issue(kt + 2);
        CP_COMMIT();
        compute(kt % 3);
    }
    CP_WAIT0();

    // -------- epilogue --------
    #pragma unroll
    for (int i = 0; i < 4; i++) {
        const int rowA = row0 + wr * 64 + i * 16 + g;
        float p0 = 0.f, p1 = 0.f;
        if (MODE != 0) {
            p0 = probs[2 * rowA + expert];
            p1 = probs[2 * (rowA + 8) + expert];
        }
        #pragma unroll
        for (int j = 0; j < 4; j++) {
            const int col = col0 + wn * 32 + j * 8 + c * 2;
            const float b0 = bias[col], b1 = bias[col + 1];
            float* out0 = C + (size_t)rowA * Nfeat + col;
            float* out1 = C + (size_t)(rowA + 8) * Nfeat + col;
            float v00 = acc[i][j][0] + b0, v01 = acc[i][j][1] + b1;
            float v10 = acc[i][j][2] + b0, v11 = acc[i][j][3] + b1;
            if (MODE == 0) {  // write tf32-rounded gelu so fc2 can cp.async raw
                out0[0] = __uint_as_float(cvt_tf32(gelu_exact(v00)));
                out0[1] = __uint_as_float(cvt_tf32(gelu_exact(v01)));
                out1[0] = __uint_as_float(cvt_tf32(gelu_exact(v10)));
                out1[1] = __uint_as_float(cvt_tf32(gelu_exact(v11)));
            } else if (MODE == 1) {
                out0[0] = p0 * v00; out0[1] = p0 * v01;
                out1[0] = p1 * v10; out1[1] = p1 * v11;
            } else {
                out0[0] += p0 * v00; out0[1] += p0 * v01;
                out1[0] += p1 * v10; out1[1] += p1 * v11;
            }
        }
    }
}

// -------------------- launch --------------------
extern "C" void kernel_launch(void* const* d_in, const int* in_sizes, int n_in,
                              void* d_out, int out_size) {
    const float* x        = (const float*)d_in[0];
    const float* router_w = (const float*)d_in[1];
    const float* router_b = (const float*)d_in[2];
    const float* light_w1 = (const float*)d_in[3];
    const float* light_b1 = (const float*)d_in[4];
    const float* light_w2 = (const float*)d_in[5];
    const float* light_b2 = (const float*)d_in[6];
    const float* heavy_w1 = (const float*)d_in[7];
    const float* heavy_b1 = (const float*)d_in[8];
    const float* heavy_w2 = (const float*)d_in[9];
    const float* heavy_b2 = (const float*)d_in[10];
    float* out = (float*)d_out;

    float *hl, *hh, *probs, *xr, *lw1r, *hw1r, *lw2r, *hw2r;
    cudaGetSymbolAddress((void**)&hl, g_hl);
    cudaGetSymbolAddress((void**)&hh, g_hh);
    cudaGetSymbolAddress((void**)&probs, g_probs);
    cudaGetSymbolAddress((void**)&xr, g_xr);
    cudaGetSymbolAddress((void**)&lw1r, g_lw1r);
    cudaGetSymbolAddress((void**)&hw1r, g_hw1r);
    cudaGetSymbolAddress((void**)&lw2r, g_lw2r);
    cudaGetSymbolAddress((void**)&hw2r, g_hw2r);

    static bool attr_done = false;
    if (!attr_done) {
        cudaFuncSetAttribute(gemm_cp_kernel<0>, cudaFuncAttributeMaxDynamicSharedMemorySize, SMEM_BYTES);
        cudaFuncSetAttribute(gemm_cp_kernel<1>, cudaFuncAttributeMaxDynamicSharedMemorySize, SMEM_BYTES);
        cudaFuncSetAttribute(gemm_cp_kernel<2>, cudaFuncAttributeMaxDynamicSharedMemorySize, SMEM_BYTES);
        attr_done = true;
    }

    router_kernel<<<N_TOK / 8, 256>>>(x, router_w, router_b, probs);

    // pre-round inputs/weights to tf32 (RTN)
    {
        int n;
        n = N_TOK * HDIM / 4;  round_kernel<<<(n + 255) / 256, 256>>>(x, xr, n);
        n = LIGHT * HDIM / 4;  round_kernel<<<(n + 255) / 256, 256>>>(light_w1, lw1r, n);
        n = HEAVY * HDIM / 4;  round_kernel<<<(n + 255) / 256, 256>>>(heavy_w1, hw1r, n);
        n = HDIM * LIGHT / 4;  round_kernel<<<(n + 255) / 256, 256>>>(light_w2, lw2r, n);
        n = HDIM * HEAVY / 4;  round_kernel<<<(n + 255) / 256, 256>>>(heavy_w2, hw2r, n);
    }

    // fc1 (gelu fused, outputs tf32-rounded)
    {
        dim3 grid(LIGHT / 128, N_TOK / 128);
        gemm_cp_kernel<0><<<grid, 256, SMEM_BYTES>>>(xr, lw1r, light_b1, hl, nullptr, 0, LIGHT, HDIM);
    }
    {
        dim3 grid(HEAVY / 128, N_TOK / 128);
        gemm_cp_kernel<0><<<grid, 256, SMEM_BYTES>>>(xr, hw1r, heavy_b1, hh, nullptr, 0, HEAVY, HDIM);
    }
    // fc2 (prob-weighted combine fused)
    {
        dim3 grid(HDIM / 128, N_TOK / 128);
        gemm_cp_kernel<1><<<grid, 256, SMEM_BYTES>>>(hl, lw2r, light_b2, out, probs, 0, HDIM, LIGHT);
    }
    {
        dim3 grid(HDIM / 128, N_TOK / 128);
        gemm_cp_kernel<2><<<grid, 256, SMEM_BYTES>>>(hh, hw2r, heavy_b2, out, probs, 1, HDIM, HEAVY);
    }
}

// round 5
// speedup vs baseline: 5.7836x; 1.5042x over previous
#include <cuda_runtime.h>
#include <cuda_fp16.h>
#include <math.h>
#include <stdint.h>

// ---------------- problem constants ----------------
#define N_TOK 32768
#define HDIM  1152
#define LIGHT 1152
#define HEAVY 4608

// ---------------- static scratch (fp16 operands) ----------------
__device__ __half g_hl [(size_t)N_TOK * LIGHT];
__device__ __half g_hh [(size_t)N_TOK * HEAVY];
__device__ __half g_xh [(size_t)N_TOK * HDIM];
__device__ __half g_lw1h[(size_t)LIGHT * HDIM];
__device__ __half g_hw1h[(size_t)HEAVY * HDIM];
__device__ __half g_lw2h[(size_t)HDIM * LIGHT];
__device__ __half g_hw2h[(size_t)HDIM * HEAVY];
__device__ float  g_probs[2 * N_TOK];

__device__ __forceinline__ uint32_t smem_u32(const void* p) {
    uint32_t a;
    asm("{ .reg .u64 t; cvta.to.shared.u64 t, %1; cvt.u32.u64 %0, t; }" : "=r"(a) : "l"(p));
    return a;
}
__device__ __forceinline__ void cp_async16(uint32_t s, const void* g) {
    size_t gp = __cvta_generic_to_global(g);
    asm volatile("cp.async.cg.shared.global [%0], [%1], 16;" :: "r"(s), "l"(gp) : "memory");
}
#define CP_COMMIT() asm volatile("cp.async.commit_group;" ::: "memory")
#define CP_WAIT1()  asm volatile("cp.async.wait_group 1;" ::: "memory")
#define CP_WAIT0()  asm volatile("cp.async.wait_group 0;" ::: "memory")

__device__ __forceinline__ void ldmatrix_x4(uint32_t& r0, uint32_t& r1,
                                            uint32_t& r2, uint32_t& r3, uint32_t addr) {
    asm volatile("ldmatrix.sync.aligned.m8n8.x4.shared.b16 {%0,%1,%2,%3}, [%4];"
                 : "=r"(r0), "=r"(r1), "=r"(r2), "=r"(r3) : "r"(addr));
}
__device__ __forceinline__ void mma_f16(float* d, const uint32_t* a, const uint32_t* b) {
    asm volatile(
        "mma.sync.aligned.m16n8k16.row.col.f32.f16.f16.f32 "
        "{%0,%1,%2,%3}, {%4,%5,%6,%7}, {%8,%9}, {%0,%1,%2,%3};"
        : "+f"(d[0]), "+f"(d[1]), "+f"(d[2]), "+f"(d[3])
        : "r"(a[0]), "r"(a[1]), "r"(a[2]), "r"(a[3]), "r"(b[0]), "r"(b[1]));
}

__device__ __forceinline__ float gelu_exact(float v) {
    return 0.5f * v * (1.0f + erff(v * 0.70710678118654752f));
}

// -------------------- fp32 -> fp16 pre-round --------------------
__global__ void round16_kernel(const float* __restrict__ in, __half* __restrict__ outp, int n4) {
    int i = blockIdx.x * blockDim.x + threadIdx.x;
    if (i < n4) {
        float4 v = ((const float4*)in)[i];
        __half2 h0 = __floats2half2_rn(v.x, v.y);
        __half2 h1 = __floats2half2_rn(v.z, v.w);
        ((__half2*)outp)[2 * i]     = h0;
        ((__half2*)outp)[2 * i + 1] = h1;
    }
}

// -------------------- router --------------------
__global__ void router_kernel(const float* __restrict__ x,
                              const float* __restrict__ rw,
                              const float* __restrict__ rb,
                              float* __restrict__ probs) {
    int warp = (blockIdx.x * blockDim.x + threadIdx.x) >> 5;
    int lane = threadIdx.x & 31;
    if (warp >= N_TOK) return;
    const float* xp = x + (size_t)warp * HDIM;
    float a0 = 0.f, a1 = 0.f;
    #pragma unroll 4
    for (int h = lane; h < HDIM; h += 32) {
        float v = xp[h];
        a0 = fmaf(v, rw[h], a0);
        a1 = fmaf(v, rw[HDIM + h], a1);
    }
    #pragma unroll
    for (int off = 16; off; off >>= 1) {
        a0 += __shfl_xor_sync(0xffffffffu, a0, off);
        a1 += __shfl_xor_sync(0xffffffffu, a1, off);
    }
    if (lane == 0) {
        a0 += rb[0];
        a1 += rb[1];
        float m = fmaxf(a0, a1);
        float e0 = __expf(a0 - m), e1 = __expf(a1 - m);
        float inv = 1.0f / (e0 + e1);
        probs[2 * warp]     = e0 * inv;
        probs[2 * warp + 1] = e1 * inv;
    }
}

// -------------------- fp16 mma GEMM (cp.async + ldmatrix) --------------------
// C[n,m] = epi( sum_k A[n,k]*W[m,k] + bias[m] ),  A/W fp16, acc fp32.
// BM=128 x BN=128 x BK=64, 256 threads (8 warps, 2x4), warp tile 64x32,
// mma m16n8k16. Smem row = 64 halves = 128B, swizzle 16B-unit s -> s^(row&7).
// MODE 0: gelu -> fp16 out; MODE 1: p*(.) overwrite fp32; MODE 2: += p*(.) fp32.
#define STAGE_B 32768
#define SMEM_BYTES (3 * STAGE_B)

template <int MODE, typename OutT>
__global__ void __launch_bounds__(256, 2) gemm_f16_kernel(
    const __half* __restrict__ A, const __half* __restrict__ W,
    const float* __restrict__ bias, OutT* __restrict__ C,
    const float* __restrict__ probs, int expert, int Nfeat, int K)
{
    extern __shared__ char smc[];
    const uint32_t sbase = smem_u32(smc);
    const int tid  = threadIdx.x;
    const int wid  = tid >> 5, lane = tid & 31;
    const int wr   = wid >> 2;      // 0..1 : 64-row group
    const int wn   = wid & 3;       // 0..3 : 32-col group
    const int g    = lane >> 2;     // 0..7
    const int c    = lane & 3;      // 0..3
    const int row0 = blockIdx.y * 128;
    const int col0 = blockIdx.x * 128;

    // ---- cp.async mapping: idx = tid + i*256 -> row=idx>>3 (0..127), s=idx&7
    const int lrow = tid >> 3;          // base row (stride 32 across i)
    const int ls   = tid & 7;           // 16B unit
    uint32_t dstA[4], dstW[4];
    #pragma unroll
    for (int i = 0; i < 4; i++) {
        int r = lrow + i * 32;
        uint32_t off = (uint32_t)(r * 128 + ((ls ^ (r & 7)) * 16));
        dstA[i] = sbase + off;
        dstW[i] = sbase + 16384u + off;
    }
    const __half* srcA0 = A + (size_t)(row0 + lrow) * K + ls * 8;
    const __half* srcW0 = W + (size_t)(col0 + lrow) * K + ls * 8;

    // ---- ldmatrix per-lane address components
    // A: rows arow + i*16, unit = ks*2 + (lane>>4)
    const int arow = wr * 64 + (lane & 15);
    const int asel = lane >> 4;
    // B: rows nrow + j2*16, unit = ks*2 + ((lane>>3)&1)
    const int nrow = wn * 32 + (lane & 7) + ((lane >> 4) << 3);
    const int bsel = (lane >> 3) & 1;

    float acc[4][4][4];
    #pragma unroll
    for (int i = 0; i < 4; i++)
        #pragma unroll
        for (int j = 0; j < 4; j++)
            #pragma unroll
            for (int q = 0; q < 4; q++) acc[i][j][q] = 0.f;

    auto issue = [&](int kt) {
        const uint32_t so = (uint32_t)(kt % 3) * STAGE_B;
        const int ko = kt * 64;
        #pragma unroll
        for (int i = 0; i < 4; i++) {
            cp_async16(dstA[i] + so, srcA0 + (size_t)(i * 32) * K + ko);
            cp_async16(dstW[i] + so, srcW0 + (size_t)(i * 32) * K + ko);
        }
    };

    auto compute = [&](int st) {
        const uint32_t as = sbase + (uint32_t)st * STAGE_B;
        const uint32_t ws = as + 16384u;
        #pragma unroll
        for (int ks = 0; ks < 4; ks++) {
            const int ua = ks * 2 + asel;
            const int ub = ks * 2 + bsel;
            uint32_t af[4][4], bf[2][4];
            #pragma unroll
            for (int i = 0; i < 4; i++) {
                int r = arow + i * 16;
                uint32_t addr = as + (uint32_t)(r * 128 + ((ua ^ (r & 7)) * 16));
                ldmatrix_x4(af[i][0], af[i][1], af[i][2], af[i][3], addr);
            }
            #pragma unroll
            for (int j2 = 0; j2 < 2; j2++) {
                int r = nrow + j2 * 16;
                uint32_t addr = ws + (uint32_t)(r * 128 + ((ub ^ (r & 7)) * 16));
                ldmatrix_x4(bf[j2][0], bf[j2][1], bf[j2][2], bf[j2][3], addr);
            }
            #pragma unroll
            for (int i = 0; i < 4; i++) {
                #pragma unroll
                for (int j = 0; j < 4; j++)
                    mma_f16(acc[i][j], af[i], &bf[j >> 1][(j & 1) * 2]);
            }
        }
    };

    const int KT = K >> 6;
    issue(0); CP_COMMIT();
    issue(1); CP_COMMIT();

    for (int kt = 0; kt < KT; kt++) {
        CP_WAIT1();
        __syncthreads();
        if (kt + 2 < KT) issue(kt + 2);
        CP_COMMIT();
        compute(kt % 3);
    }
    CP_WAIT0();

    // -------- epilogue --------
    #pragma unroll
    for (int i = 0; i < 4; i++) {
        const int rowA = row0 + wr * 64 + i * 16 + g;
        float p0 = 0.f, p1 = 0.f;
        if (MODE != 0) {
            p0 = probs[2 * rowA + expert];
            p1 = probs[2 * (rowA + 8) + expert];
        }
        #pragma unroll
        for (int j = 0; j < 4; j++) {
            const int col = col0 + wn * 32 + j * 8 + c * 2;
            const float b0 = bias[col], b1 = bias[col + 1];
            OutT* out0 = C + (size_t)rowA * Nfeat + col;
            OutT* out1 = C + (size_t)(rowA + 8) * Nfeat + col;
            float v00 = acc[i][j][0] + b0, v01 = acc[i][j][1] + b1;
            float v10 = acc[i][j][2] + b0, v11 = acc[i][j][3] + b1;
            if (MODE == 0) {
                *(__half2*)out0 = __floats2half2_rn(gelu_exact(v00), gelu_exact(v01));
                *(__half2*)out1 = __floats2half2_rn(gelu_exact(v10), gelu_exact(v11));
            } else if (MODE == 1) {
                out0[0] = p0 * v00; out0[1] = p0 * v01;
                out1[0] = p1 * v10; out1[1] = p1 * v11;
            } else {
                out0[0] += p0 * v00; out0[1] += p0 * v01;
                out1[0] += p1 * v10; out1[1] += p1 * v11;
            }
        }
    }
}

// -------------------- launch --------------------
extern "C" void kernel_launch(void* const* d_in, const int* in_sizes, int n_in,
                              void* d_out, int out_size) {
    const float* x        = (const float*)d_in[0];
    const float* router_w = (const float*)d_in[1];
    const float* router_b = (const float*)d_in[2];
    const float* light_w1 = (const float*)d_in[3];
    const float* light_b1 = (const float*)d_in[4];
    const float* light_w2 = (const float*)d_in[5];
    const float* light_b2 = (const float*)d_in[6];
    const float* heavy_w1 = (const float*)d_in[7];
    const float* heavy_b1 = (const float*)d_in[8];
    const float* heavy_w2 = (const float*)d_in[9];
    const float* heavy_b2 = (const float*)d_in[10];
    float* out = (float*)d_out;

    __half *hl, *hh, *xh, *lw1h, *hw1h, *lw2h, *hw2h;
    float* probs;
    cudaGetSymbolAddress((void**)&hl, g_hl);
    cudaGetSymbolAddress((void**)&hh, g_hh);
    cudaGetSymbolAddress((void**)&xh, g_xh);
    cudaGetSymbolAddress((void**)&lw1h, g_lw1h);
    cudaGetSymbolAddress((void**)&hw1h, g_hw1h);
    cudaGetSymbolAddress((void**)&lw2h, g_lw2h);
    cudaGetSymbolAddress((void**)&hw2h, g_hw2h);
    cudaGetSymbolAddress((void**)&probs, g_probs);

    static bool attr_done = false;
    if (!attr_done) {
        cudaFuncSetAttribute((const void*)gemm_f16_kernel<0, __half>,
                             cudaFuncAttributeMaxDynamicSharedMemorySize, SMEM_BYTES);
        cudaFuncSetAttribute((const void*)gemm_f16_kernel<1, float>,
                             cudaFuncAttributeMaxDynamicSharedMemorySize, SMEM_BYTES);
        cudaFuncSetAttribute((const void*)gemm_f16_kernel<2, float>,
                             cudaFuncAttributeMaxDynamicSharedMemorySize, SMEM_BYTES);
        attr_done = true;
    }

    router_kernel<<<N_TOK / 8, 256>>>(x, router_w, router_b, probs);

    // pre-round to fp16 (RTN)
    {
        int n;
        n = N_TOK * HDIM / 4;  round16_kernel<<<(n + 255) / 256, 256>>>(x, xh, n);
        n = LIGHT * HDIM / 4;  round16_kernel<<<(n + 255) / 256, 256>>>(light_w1, lw1h, n);
        n = HEAVY * HDIM / 4;  round16_kernel<<<(n + 255) / 256, 256>>>(heavy_w1, hw1h, n);
        n = HDIM * LIGHT / 4;  round16_kernel<<<(n + 255) / 256, 256>>>(light_w2, lw2h, n);
        n = HDIM * HEAVY / 4;  round16_kernel<<<(n + 255) / 256, 256>>>(heavy_w2, hw2h, n);
    }

    // fc1 (gelu fused, fp16 outputs)
    {
        dim3 grid(LIGHT / 128, N_TOK / 128);
        gemm_f16_kernel<0, __half><<<grid, 256, SMEM_BYTES>>>(xh, lw1h, light_b1, hl, nullptr, 0, LIGHT, HDIM);
    }
    {
        dim3 grid(HEAVY / 128, N_TOK / 128);
        gemm_f16_kernel<0, __half><<<grid, 256, SMEM_BYTES>>>(xh, hw1h, heavy_b1, hh, nullptr, 0, HEAVY, HDIM);
    }
    // fc2 (prob-weighted combine fused, fp32 output)
    {
        dim3 grid(HDIM / 128, N_TOK / 128);
        gemm_f16_kernel<1, float><<<grid, 256, SMEM_BYTES>>>(hl, lw2h, light_b2, out, probs, 0, HDIM, LIGHT);
    }
    {
        dim3 grid(HDIM / 128, N_TOK / 128);
        gemm_f16_kernel<2, float><<<grid, 256, SMEM_BYTES>>>(hh, hw2h, heavy_b2, out, probs, 1, HDIM, HEAVY);
    }
}

// round 6
// speedup vs baseline: 8.8468x; 1.5296x over previous
#include <cuda_runtime.h>
#include <cuda_fp16.h>
#include <math.h>
#include <stdint.h>

// ---------------- problem constants ----------------
#define N_TOK 32768
#define HDIM  1152
#define LIGHT 1152
#define HEAVY 4608

// ---------------- static scratch (fp16 operands) ----------------
__device__ __half g_hl [(size_t)N_TOK * LIGHT];
__device__ __half g_hh [(size_t)N_TOK * HEAVY];
__device__ __half g_xh [(size_t)N_TOK * HDIM];
__device__ __half g_lw1h[(size_t)LIGHT * HDIM];
__device__ __half g_hw1h[(size_t)HEAVY * HDIM];
__device__ __half g_lw2h[(size_t)HDIM * LIGHT];
__device__ __half g_hw2h[(size_t)HDIM * HEAVY];
__device__ float  g_probs[2 * N_TOK];

__device__ __forceinline__ uint32_t smem_u32(const void* p) {
    uint32_t a;
    asm("{ .reg .u64 t; cvta.to.shared.u64 t, %1; cvt.u32.u64 %0, t; }" : "=r"(a) : "l"(p));
    return a;
}
__device__ __forceinline__ void cp_async16(uint32_t s, const void* g) {
    size_t gp = __cvta_generic_to_global(g);
    asm volatile("cp.async.cg.shared.global [%0], [%1], 16;" :: "r"(s), "l"(gp) : "memory");
}
#define CP_COMMIT() asm volatile("cp.async.commit_group;" ::: "memory")
#define CP_WAIT1()  asm volatile("cp.async.wait_group 1;" ::: "memory")
#define CP_WAIT0()  asm volatile("cp.async.wait_group 0;" ::: "memory")

__device__ __forceinline__ void ldmatrix_x4(uint32_t& r0, uint32_t& r1,
                                            uint32_t& r2, uint32_t& r3, uint32_t addr) {
    asm volatile("ldmatrix.sync.aligned.m8n8.x4.shared.b16 {%0,%1,%2,%3}, [%4];"
                 : "=r"(r0), "=r"(r1), "=r"(r2), "=r"(r3) : "r"(addr));
}
__device__ __forceinline__ void mma_f16(float* d, const uint32_t* a, const uint32_t* b) {
    asm volatile(
        "mma.sync.aligned.m16n8k16.row.col.f32.f16.f16.f32 "
        "{%0,%1,%2,%3}, {%4,%5,%6,%7}, {%8,%9}, {%0,%1,%2,%3};"
        : "+f"(d[0]), "+f"(d[1]), "+f"(d[2]), "+f"(d[3])
        : "r"(a[0]), "r"(a[1]), "r"(a[2]), "r"(a[3]), "r"(b[0]), "r"(b[1]));
}

__device__ __forceinline__ float gelu_exact(float v) {
    return 0.5f * v * (1.0f + erff(v * 0.70710678118654752f));
}

// -------------------- fp32 -> fp16 pre-round --------------------
__global__ void round16_kernel(const float* __restrict__ in, __half* __restrict__ outp, int n4) {
    int i = blockIdx.x * blockDim.x + threadIdx.x;
    if (i < n4) {
        float4 v = ((const float4*)in)[i];
        __half2 h0 = __floats2half2_rn(v.x, v.y);
        __half2 h1 = __floats2half2_rn(v.z, v.w);
        ((__half2*)outp)[2 * i]     = h0;
        ((__half2*)outp)[2 * i + 1] = h1;
    }
}

// -------------------- router --------------------
__global__ void router_kernel(const float* __restrict__ x,
                              const float* __restrict__ rw,
                              const float* __restrict__ rb,
                              float* __restrict__ probs) {
    int warp = (blockIdx.x * blockDim.x + threadIdx.x) >> 5;
    int lane = threadIdx.x & 31;
    if (warp >= N_TOK) return;
    const float* xp = x + (size_t)warp * HDIM;
    float a0 = 0.f, a1 = 0.f;
    #pragma unroll 4
    for (int h = lane; h < HDIM; h += 32) {
        float v = xp[h];
        a0 = fmaf(v, rw[h], a0);
        a1 = fmaf(v, rw[HDIM + h], a1);
    }
    #pragma unroll
    for (int off = 16; off; off >>= 1) {
        a0 += __shfl_xor_sync(0xffffffffu, a0, off);
        a1 += __shfl_xor_sync(0xffffffffu, a1, off);
    }
    if (lane == 0) {
        a0 += rb[0];
        a1 += rb[1];
        float m = fmaxf(a0, a1);
        float e0 = __expf(a0 - m), e1 = __expf(a1 - m);
        float inv = 1.0f / (e0 + e1);
        probs[2 * warp]     = e0 * inv;
        probs[2 * warp + 1] = e1 * inv;
    }
}

// -------------------- fp16 mma GEMM (cp.async + ldmatrix) --------------------
// C[n,m] = epi( sum_k A[n,k]*W[m,k] + bias[m] ),  A/W fp16, acc fp32.
// BM=128 x BN=128 x BK=64, 256 threads (8 warps, 2x4), warp tile 64x32,
// mma m16n8k16. Smem row = 64 halves = 128B, swizzle 16B-unit s -> s^(row&7).
// MODE 0: gelu -> fp16 out; MODE 1: p*(.) overwrite fp32; MODE 2: += p*(.) fp32.
#define STAGE_B 32768
#define SMEM_BYTES (3 * STAGE_B)

template <int MODE, typename OutT>
__global__ void __launch_bounds__(256, 2) gemm_f16_kernel(
    const __half* __restrict__ A, const __half* __restrict__ W,
    const float* __restrict__ bias, OutT* __restrict__ C,
    const float* __restrict__ probs, int expert, int Nfeat, int K)
{
    extern __shared__ char smc[];
    const uint32_t sbase = smem_u32(smc);
    const int tid  = threadIdx.x;
    const int wid  = tid >> 5, lane = tid & 31;
    const int wr   = wid >> 2;      // 0..1 : 64-row group
    const int wn   = wid & 3;       // 0..3 : 32-col group
    const int g    = lane >> 2;     // 0..7
    const int c    = lane & 3;      // 0..3
    const int row0 = blockIdx.y * 128;
    const int col0 = blockIdx.x * 128;

    // ---- cp.async mapping: idx = tid + i*256 -> row=idx>>3 (0..127), s=idx&7
    const int lrow = tid >> 3;          // base row (stride 32 across i)
    const int ls   = tid & 7;           // 16B unit
    uint32_t dstA[4], dstW[4];
    #pragma unroll
    for (int i = 0; i < 4; i++) {
        int r = lrow + i * 32;
        uint32_t off = (uint32_t)(r * 128 + ((ls ^ (r & 7)) * 16));
        dstA[i] = sbase + off;
        dstW[i] = sbase + 16384u + off;
    }
    const __half* srcA0 = A + (size_t)(row0 + lrow) * K + ls * 8;
    const __half* srcW0 = W + (size_t)(col0 + lrow) * K + ls * 8;

    // ---- ldmatrix per-lane address components
    // A: rows arow + i*16, unit = ks*2 + (lane>>4)
    const int arow = wr * 64 + (lane & 15);
    const int asel = lane >> 4;
    // B: rows nrow + j2*16, unit = ks*2 + ((lane>>3)&1)
    const int nrow = wn * 32 + (lane & 7) + ((lane >> 4) << 3);
    const int bsel = (lane >> 3) & 1;

    float acc[4][4][4];
    #pragma unroll
    for (int i = 0; i < 4; i++)
        #pragma unroll
        for (int j = 0; j < 4; j++)
            #pragma unroll
            for (int q = 0; q < 4; q++) acc[i][j][q] = 0.f;

    auto issue = [&](int kt) {
        const uint32_t so = (uint32_t)(kt % 3) * STAGE_B;
        const int ko = kt * 64;
        #pragma unroll
        for (int i = 0; i < 4; i++) {
            cp_async16(dstA[i] + so, srcA0 + (size_t)(i * 32) * K + ko);
            cp_async16(dstW[i] + so, srcW0 + (size_t)(i * 32) * K + ko);
        }
    };

    auto compute = [&](int st) {
        const uint32_t as = sbase + (uint32_t)st * STAGE_B;
        const uint32_t ws = as + 16384u;
        #pragma unroll
        for (int ks = 0; ks < 4; ks++) {
            const int ua = ks * 2 + asel;
            const int ub = ks * 2 + bsel;
            uint32_t af[4][4], bf[2][4];
            #pragma unroll
            for (int i = 0; i < 4; i++) {
                int r = arow + i * 16;
                uint32_t addr = as + (uint32_t)(r * 128 + ((ua ^ (r & 7)) * 16));
                ldmatrix_x4(af[i][0], af[i][1], af[i][2], af[i][3], addr);
            }
            #pragma unroll
            for (int j2 = 0; j2 < 2; j2++) {
                int r = nrow + j2 * 16;
                uint32_t addr = ws + (uint32_t)(r * 128 + ((ub ^ (r & 7)) * 16));
                ldmatrix_x4(bf[j2][0], bf[j2][1], bf[j2][2], bf[j2][3], addr);
            }
            #pragma unroll
            for (int i = 0; i < 4; i++) {
                #pragma unroll
                for (int j = 0; j < 4; j++)
                    mma_f16(acc[i][j], af[i], &bf[j >> 1][(j & 1) * 2]);
            }
        }
    };

    const int KT = K >> 6;
    issue(0); CP_COMMIT();
    issue(1); CP_COMMIT();

    for (int kt = 0; kt < KT; kt++) {
        CP_WAIT1();
        __syncthreads();
        if (kt + 2 < KT) issue(kt + 2);
        CP_COMMIT();
        compute(kt % 3);
    }
    CP_WAIT0();

    // -------- epilogue --------
    #pragma unroll
    for (int i = 0; i < 4; i++) {
        const int rowA = row0 + wr * 64 + i * 16 + g;
        float p0 = 0.f, p1 = 0.f;
        if (MODE != 0) {
            p0 = probs[2 * rowA + expert];
            p1 = probs[2 * (rowA + 8) + expert];
        }
        #pragma unroll
        for (int j = 0; j < 4; j++) {
            const int col = col0 + wn * 32 + j * 8 + c * 2;
            const float b0 = bias[col], b1 = bias[col + 1];
            OutT* out0 = C + (size_t)rowA * Nfeat + col;
            OutT* out1 = C + (size_t)(rowA + 8) * Nfeat + col;
            float v00 = acc[i][j][0] + b0, v01 = acc[i][j][1] + b1;
            float v10 = acc[i][j][2] + b0, v11 = acc[i][j][3] + b1;
            if (MODE == 0) {
                *(__half2*)out0 = __floats2half2_rn(gelu_exact(v00), gelu_exact(v01));
                *(__half2*)out1 = __floats2half2_rn(gelu_exact(v10), gelu_exact(v11));
            } else if (MODE == 1) {
                out0[0] = p0 * v00; out0[1] = p0 * v01;
                out1[0] = p1 * v10; out1[1] = p1 * v11;
            } else {
                out0[0] += p0 * v00; out0[1] += p0 * v01;
                out1[0] += p1 * v10; out1[1] += p1 * v11;
            }
        }
    }
}

// -------------------- launch --------------------
extern "C" void kernel_launch(void* const* d_in, const int* in_sizes, int n_in,
                              void* d_out, int out_size) {
    const float* x        = (const float*)d_in[0];
    const float* router_w = (const float*)d_in[1];
    const float* router_b = (const float*)d_in[2];
    const float* light_w1 = (const float*)d_in[3];
    const float* light_b1 = (const float*)d_in[4];
    const float* light_w2 = (const float*)d_in[5];
    const float* light_b2 = (const float*)d_in[6];
    const float* heavy_w1 = (const float*)d_in[7];
    const float* heavy_b1 = (const float*)d_in[8];
    const float* heavy_w2 = (const float*)d_in[9];
    const float* heavy_b2 = (const float*)d_in[10];
    float* out = (float*)d_out;

    __half *hl, *hh, *xh, *lw1h, *hw1h, *lw2h, *hw2h;
    float* probs;
    cudaGetSymbolAddress((void**)&hl, g_hl);
    cudaGetSymbolAddress((void**)&hh, g_hh);
    cudaGetSymbolAddress((void**)&xh, g_xh);
    cudaGetSymbolAddress((void**)&lw1h, g_lw1h);
    cudaGetSymbolAddress((void**)&hw1h, g_hw1h);
    cudaGetSymbolAddress((void**)&lw2h, g_lw2h);
    cudaGetSymbolAddress((void**)&hw2h, g_hw2h);
    cudaGetSymbolAddress((void**)&probs, g_probs);

    static bool attr_done = false;
    if (!attr_done) {
        cudaFuncSetAttribute((const void*)gemm_f16_kernel<0, __half>,
                             cudaFuncAttributeMaxDynamicSharedMemorySize, SMEM_BYTES);
        cudaFuncSetAttribute((const void*)gemm_f16_kernel<1, float>,
                             cudaFuncAttributeMaxDynamicSharedMemorySize, SMEM_BYTES);
        cudaFuncSetAttribute((const void*)gemm_f16_kernel<2, float>,
                             cudaFuncAttributeMaxDynamicSharedMemorySize, SMEM_BYTES);
        attr_done = true;
    }

    router_kernel<<<N_TOK / 8, 256>>>(x, router_w, router_b, probs);

    // pre-round to fp16 (RTN)
    {
        int n;
        n = N_TOK * HDIM / 4;  round16_kernel<<<(n + 255) / 256, 256>>>(x, xh, n);
        n = LIGHT * HDIM / 4;  round16_kernel<<<(n + 255) / 256, 256>>>(light_w1, lw1h, n);
        n = HEAVY * HDIM / 4;  round16_kernel<<<(n + 255) / 256, 256>>>(heavy_w1, hw1h, n);
        n = HDIM * LIGHT / 4;  round16_kernel<<<(n + 255) / 256, 256>>>(light_w2, lw2h, n);
        n = HDIM * HEAVY / 4;  round16_kernel<<<(n + 255) / 256, 256>>>(heavy_w2, hw2h, n);
    }

    // fc1 (gelu fused, fp16 outputs)
    {
        dim3 grid(LIGHT / 128, N_TOK / 128);
        gemm_f16_kernel<0, __half><<<grid, 256, SMEM_BYTES>>>(xh, lw1h, light_b1, hl, nullptr, 0, LIGHT, HDIM);
    }
    {
        dim3 grid(HEAVY / 128, N_TOK / 128);
        gemm_f16_kernel<0, __half><<<grid, 256, SMEM_BYTES>>>(xh, hw1h, heavy_b1, hh, nullptr, 0, HEAVY, HDIM);
    }
    // fc2 (prob-weighted combine fused, fp32 output)
    {
        dim3 grid(HDIM / 128, N_TOK / 128);
        gemm_f16_kernel<1, float><<<grid, 256, SMEM_BYTES>>>(hl, lw2h, light_b2, out, probs, 0, HDIM, LIGHT);
    }
    {
        dim3 grid(HDIM / 128, N_TOK / 128);
        gemm_f16_kernel<2, float><<<grid, 256, SMEM_BYTES>>>(hh, hw2h, heavy_b2, out, probs, 1, HDIM, HEAVY);
    }
}

// round 7
// speedup vs baseline: 9.6778x; 1.0939x over previous
#include <cuda_runtime.h>
#include <cuda_fp16.h>
#include <math.h>
#include <stdint.h>

// ---------------- problem constants ----------------
#define N_TOK 32768
#define HDIM  1152
#define LIGHT 1152
#define HEAVY 4608

// ---------------- static scratch (fp16 operands) ----------------
__device__ __half g_hl [(size_t)N_TOK * LIGHT];   // p0 * gelu(fc1_light)
__device__ __half g_hh [(size_t)N_TOK * HEAVY];   // p1 * gelu(fc1_heavy)
__device__ __half g_xh [(size_t)N_TOK * HDIM];
__device__ __half g_lw1h[(size_t)LIGHT * HDIM];
__device__ __half g_hw1h[(size_t)HEAVY * HDIM];
__device__ __half g_lw2h[(size_t)HDIM * LIGHT];
__device__ __half g_hw2h[(size_t)HDIM * HEAVY];
__device__ float  g_probs[2 * N_TOK];

__device__ __forceinline__ uint32_t smem_u32(const void* p) {
    uint32_t a;
    asm("{ .reg .u64 t; cvta.to.shared.u64 t, %1; cvt.u32.u64 %0, t; }" : "=r"(a) : "l"(p));
    return a;
}
__device__ __forceinline__ void cp_async16(uint32_t s, const void* g) {
    size_t gp = __cvta_generic_to_global(g);
    asm volatile("cp.async.cg.shared.global [%0], [%1], 16;" :: "r"(s), "l"(gp) : "memory");
}
#define CP_COMMIT() asm volatile("cp.async.commit_group;" ::: "memory")
#define CP_WAIT1()  asm volatile("cp.async.wait_group 1;" ::: "memory")
#define CP_WAIT0()  asm volatile("cp.async.wait_group 0;" ::: "memory")

__device__ __forceinline__ void ldmatrix_x4(uint32_t& r0, uint32_t& r1,
                                            uint32_t& r2, uint32_t& r3, uint32_t addr) {
    asm volatile("ldmatrix.sync.aligned.m8n8.x4.shared.b16 {%0,%1,%2,%3}, [%4];"
                 : "=r"(r0), "=r"(r1), "=r"(r2), "=r"(r3) : "r"(addr));
}
__device__ __forceinline__ void mma_f16(float* d, const uint32_t* a, const uint32_t* b) {
    asm volatile(
        "mma.sync.aligned.m16n8k16.row.col.f32.f16.f16.f32 "
        "{%0,%1,%2,%3}, {%4,%5,%6,%7}, {%8,%9}, {%0,%1,%2,%3};"
        : "+f"(d[0]), "+f"(d[1]), "+f"(d[2]), "+f"(d[3])
        : "r"(a[0]), "r"(a[1]), "r"(a[2]), "r"(a[3]), "r"(b[0]), "r"(b[1]));
}

__device__ __forceinline__ float gelu_exact(float v) {
    return 0.5f * v * (1.0f + erff(v * 0.70710678118654752f));
}

// -------------------- fp32 -> fp16 weight pre-round --------------------
__global__ void round16_kernel(const float* __restrict__ in, __half* __restrict__ outp, int n4) {
    int i = blockIdx.x * blockDim.x + threadIdx.x;
    if (i < n4) {
        float4 v = ((const float4*)in)[i];
        ((__half2*)outp)[2 * i]     = __floats2half2_rn(v.x, v.y);
        ((__half2*)outp)[2 * i + 1] = __floats2half2_rn(v.z, v.w);
    }
}

// -------------------- router (also converts x -> fp16) --------------------
__global__ void router_kernel(const float* __restrict__ x,
                              const float* __restrict__ rw,
                              const float* __restrict__ rb,
                              float* __restrict__ probs,
                              __half* __restrict__ xh) {
    int warp = (blockIdx.x * blockDim.x + threadIdx.x) >> 5;
    int lane = threadIdx.x & 31;
    if (warp >= N_TOK) return;
    const float* xp = x + (size_t)warp * HDIM;
    __half* xo = xh + (size_t)warp * HDIM;
    float a0 = 0.f, a1 = 0.f;
    #pragma unroll 4
    for (int h = lane; h < HDIM; h += 32) {
        float v = xp[h];
        xo[h] = __float2half_rn(v);
        a0 = fmaf(v, rw[h], a0);
        a1 = fmaf(v, rw[HDIM + h], a1);
    }
    #pragma unroll
    for (int off = 16; off; off >>= 1) {
        a0 += __shfl_xor_sync(0xffffffffu, a0, off);
        a1 += __shfl_xor_sync(0xffffffffu, a1, off);
    }
    if (lane == 0) {
        a0 += rb[0];
        a1 += rb[1];
        float m = fmaxf(a0, a1);
        float e0 = __expf(a0 - m), e1 = __expf(a1 - m);
        float inv = 1.0f / (e0 + e1);
        probs[2 * warp]     = e0 * inv;
        probs[2 * warp + 1] = e1 * inv;
    }
}

// -------------------- fp16 mma GEMM --------------------
// CTA 128x128, 4 warps (2x2), warp tile 64x64, BK=64, 3-stage cp.async, 96KB smem.
// Smem row = 64 halves = 128B; swizzle: 16B-unit s stored at s ^ (row & 7).
// MODE 0 (fc1): C[fp16] = probs[n,expert] * gelu(acc + b0[m]);  single segment.
// MODE 1 (fc2): C[fp32] = acc(seg0: hl@lw2) + acc(seg1: hh@hw2)
//                          + p0*b0[m] + p1*b1[m];  dual segment.
#define STAGE_B 32768
#define SMEM_BYTES (3 * STAGE_B)

template <int MODE, typename OutT>
__global__ void __launch_bounds__(128, 2) gemm_f16_kernel(
    const __half* __restrict__ A0, const __half* __restrict__ W0, int K0,
    const __half* __restrict__ A1, const __half* __restrict__ W1, int K1,
    const float* __restrict__ b0v, const float* __restrict__ b1v,
    OutT* __restrict__ C, const float* __restrict__ probs, int expert, int Nfeat)
{
    extern __shared__ char smc[];
    const uint32_t sbase = smem_u32(smc);
    const int tid  = threadIdx.x;
    const int wid  = tid >> 5, lane = tid & 31;
    const int wr   = wid >> 1;      // 0..1 : 64-row group
    const int wn   = wid & 1;       // 0..1 : 64-col group
    const int g    = lane >> 2;     // 0..7
    const int c    = lane & 3;      // 0..3
    const int row0 = blockIdx.y * 128;
    const int col0 = blockIdx.x * 128;

    // ---- cp.async mapping: 128 threads; lrow=tid>>3 (0..15), ls=tid&7
    const int lrow = tid >> 3;
    const int ls   = tid & 7;
    const uint32_t offA0 = (uint32_t)(lrow * 128 + ((ls ^ (lrow & 7)) * 16));

    // ---- ldmatrix lane components (row&7 constant across 16-row steps)
    const int arow = wr * 64 + (lane & 15);
    const int asel = lane >> 4;
    const int nrow = wn * 64 + (lane & 7) + ((lane >> 4) << 3);
    const int bsel = (lane >> 3) & 1;

    float acc[4][8][4];
    #pragma unroll
    for (int i = 0; i < 4; i++)
        #pragma unroll
        for (int j = 0; j < 8; j++)
            #pragma unroll
            for (int q = 0; q < 4; q++) acc[i][j][q] = 0.f;

    const int KT0 = K0 >> 6;
    const int KT  = KT0 + ((MODE == 1) ? (K1 >> 6) : 0);

    auto issue = [&](int kt) {
        const uint32_t so = (uint32_t)(kt % 3) * STAGE_B;
        const __half* a;
        const __half* w;
        int K;
        if (MODE == 0 || kt < KT0) {
            K = K0;
            a = A0 + (size_t)(row0 + lrow) * K0 + ls * 8 + kt * 64;
            w = W0 + (size_t)(col0 + lrow) * K0 + ls * 8 + kt * 64;
        } else {
            K = K1;
            int kl = kt - KT0;
            a = A1 + (size_t)(row0 + lrow) * K1 + ls * 8 + kl * 64;
            w = W1 + (size_t)(col0 + lrow) * K1 + ls * 8 + kl * 64;
        }
        #pragma unroll
        for (int i = 0; i < 8; i++) {
            cp_async16(sbase + so + offA0 + i * 2048u,          a + (size_t)(i * 16) * K);
            cp_async16(sbase + so + 16384u + offA0 + i * 2048u, w + (size_t)(i * 16) * K);
        }
    };

    auto compute = [&](int st) {
        const uint32_t as = sbase + (uint32_t)st * STAGE_B;
        const uint32_t ws = as + 16384u;
        #pragma unroll
        for (int ks = 0; ks < 4; ks++) {
            const int ua = ks * 2 + asel;
            const int ub = ks * 2 + bsel;
            uint32_t af[4][4], bf[4][4];
            #pragma unroll
            for (int i = 0; i < 4; i++) {
                int r = arow + i * 16;
                uint32_t addr = as + (uint32_t)(r * 128 + ((ua ^ (arow & 7)) * 16));
                ldmatrix_x4(af[i][0], af[i][1], af[i][2], af[i][3], addr);
            }
            #pragma unroll
            for (int j2 = 0; j2 < 4; j2++) {
                int r = nrow + j2 * 16;
                uint32_t addr = ws + (uint32_t)(r * 128 + ((ub ^ (nrow & 7)) * 16));
                ldmatrix_x4(bf[j2][0], bf[j2][1], bf[j2][2], bf[j2][3], addr);
            }
            #pragma unroll
            for (int i = 0; i < 4; i++)
                #pragma unroll
                for (int j = 0; j < 8; j++)
                    mma_f16(acc[i][j], af[i], &bf[j >> 1][(j & 1) * 2]);
        }
    };

    issue(0); CP_COMMIT();
    issue(1); CP_COMMIT();
    for (int kt = 0; kt < KT; kt++) {
        CP_WAIT1();
        __syncthreads();
        if (kt + 2 < KT) issue(kt + 2);
        CP_COMMIT();
        compute(kt % 3);
    }
    CP_WAIT0();

    // -------- epilogue --------
    #pragma unroll
    for (int i = 0; i < 4; i++) {
        const int rowA = row0 + wr * 64 + i * 16 + g;
        float p0a, p1a, p0b, p1b;
        if (MODE == 0) {
            p0a = probs[2 * rowA + expert];
            p0b = probs[2 * (rowA + 8) + expert];
            p1a = p1b = 0.f;
        } else {
            p0a = probs[2 * rowA];       p1a = probs[2 * rowA + 1];
            p0b = probs[2 * (rowA + 8)]; p1b = probs[2 * (rowA + 8) + 1];
        }
        #pragma unroll
        for (int j = 0; j < 8; j++) {
            const int col = col0 + wn * 64 + j * 8 + c * 2;
            OutT* out0 = C + (size_t)rowA * Nfeat + col;
            OutT* out1 = C + (size_t)(rowA + 8) * Nfeat + col;
            if (MODE == 0) {
                const float b0 = b0v[col], b1 = b0v[col + 1];
                *(__half2*)out0 = __floats2half2_rn(p0a * gelu_exact(acc[i][j][0] + b0),
                                                    p0a * gelu_exact(acc[i][j][1] + b1));
                *(__half2*)out1 = __floats2half2_rn(p0b * gelu_exact(acc[i][j][2] + b0),
                                                    p0b * gelu_exact(acc[i][j][3] + b1));
            } else {
                const float bl0 = b0v[col], bl1 = b0v[col + 1];
                const float bh0 = b1v[col], bh1 = b1v[col + 1];
                out0[0] = acc[i][j][0] + p0a * bl0 + p1a * bh0;
                out0[1] = acc[i][j][1] + p0a * bl1 + p1a * bh1;
                out1[0] = acc[i][j][2] + p0b * bl0 + p1b * bh0;
                out1[1] = acc[i][j][3] + p0b * bl1 + p1b * bh1;
            }
        }
    }
}

// -------------------- launch --------------------
extern "C" void kernel_launch(void* const* d_in, const int* in_sizes, int n_in,
                              void* d_out, int out_size) {
    const float* x        = (const float*)d_in[0];
    const float* router_w = (const float*)d_in[1];
    const float* router_b = (const float*)d_in[2];
    const float* light_w1 = (const float*)d_in[3];
    const float* light_b1 = (const float*)d_in[4];
    const float* light_w2 = (const float*)d_in[5];
    const float* light_b2 = (const float*)d_in[6];
    const float* heavy_w1 = (const float*)d_in[7];
    const float* heavy_b1 = (const float*)d_in[8];
    const float* heavy_w2 = (const float*)d_in[9];
    const float* heavy_b2 = (const float*)d_in[10];
    float* out = (float*)d_out;

    __half *hl, *hh, *xh, *lw1h, *hw1h, *lw2h, *hw2h;
    float* probs;
    cudaGetSymbolAddress((void**)&hl, g_hl);
    cudaGetSymbolAddress((void**)&hh, g_hh);
    cudaGetSymbolAddress((void**)&xh, g_xh);
    cudaGetSymbolAddress((void**)&lw1h, g_lw1h);
    cudaGetSymbolAddress((void**)&hw1h, g_hw1h);
    cudaGetSymbolAddress((void**)&lw2h, g_lw2h);
    cudaGetSymbolAddress((void**)&hw2h, g_hw2h);
    cudaGetSymbolAddress((void**)&probs, g_probs);

    static bool attr_done = false;
    if (!attr_done) {
        cudaFuncSetAttribute((const void*)gemm_f16_kernel<0, __half>,
                             cudaFuncAttributeMaxDynamicSharedMemorySize, SMEM_BYTES);
        cudaFuncSetAttribute((const void*)gemm_f16_kernel<1, float>,
                             cudaFuncAttributeMaxDynamicSharedMemorySize, SMEM_BYTES);
        attr_done = true;
    }

    router_kernel<<<N_TOK / 8, 256>>>(x, router_w, router_b, probs, xh);

    {   // weight conversions
        int n;
        n = LIGHT * HDIM / 4;  round16_kernel<<<(n + 255) / 256, 256>>>(light_w1, lw1h, n);
        n = HEAVY * HDIM / 4;  round16_kernel<<<(n + 255) / 256, 256>>>(heavy_w1, hw1h, n);
        n = HDIM * LIGHT / 4;  round16_kernel<<<(n + 255) / 256, 256>>>(light_w2, lw2h, n);
        n = HDIM * HEAVY / 4;  round16_kernel<<<(n + 255) / 256, 256>>>(heavy_w2, hw2h, n);
    }

    // fc1: hl = p0*gelu(x@lw1 + b), hh = p1*gelu(x@hw1 + b)   (fp16 out)
    {
        dim3 grid(LIGHT / 128, N_TOK / 128);
        gemm_f16_kernel<0, __half><<<grid, 128, SMEM_BYTES>>>(
            xh, lw1h, HDIM, nullptr, nullptr, 0, light_b1, nullptr, hl, probs, 0, LIGHT);
    }
    {
        dim3 grid(HEAVY / 128, N_TOK / 128);
        gemm_f16_kernel<0, __half><<<grid, 128, SMEM_BYTES>>>(
            xh, hw1h, HDIM, nullptr, nullptr, 0, heavy_b1, nullptr, hh, probs, 1, HEAVY);
    }
    // fc2 (dual segment): out = hl@lw2 + hh@hw2 + p0*b_l + p1*b_h
    {
        dim3 grid(HDIM / 128, N_TOK / 128);
        gemm_f16_kernel<1, float><<<grid, 128, SMEM_BYTES>>>(
            hl, lw2h, LIGHT, hh, hw2h, HEAVY, light_b2, heavy_b2, out, probs, 0, HDIM);
    }
}